// round 15
// baseline (speedup 1.0000x reference)
#include <cuda_runtime.h>
#include <math.h>

#define BATCH 128
#define HH 512
#define WW 512
#define HW (HH*WW)
#define W4R (WW/4)       // 128 float4 per image row

// Per-batch compute region: 98 rows x 112 cols (floats), one CTA per batch.
// Seed at local (49, sx), sx in [56,59]. Support after k global iterations
// is the L1-diamond of radius k (per-row forward gate). Stage 3 additionally
// gated by the backward cone of the goal. Batches with L1(start,goal)>45
// exit immediately with out=0 (exact).
#define RR 98            // region rows
#define RC 112           // region cols (floats)
#define RCF4 (RC/4)      // 28 f4 per row
#define NCOLV 26         // compute f4 columns v = 1..26
#define NGRP 12          // row groups
#define RPG 8            // rows per group: 12*8 = 96 compute rows (1..96)
#define THREADS 320      // 10 warps; tids >= 312 idle (barrier-only)
#define NWARP (THREADS/32)     // 10
#define SMEMB (2*RR*RC*4)      // 87,808 B dynamic
#define FULL 0xffffffffu

// d = clamp(a*w + c, 0, 1) in ONE instruction (FFMA.SAT)
#define FMASAT(d, a, w, c) \
    asm("fma.rn.sat.f32 %0, %1, %2, %3;" : "=f"(d) : "f"(a), "f"(w), "f"(c))

__global__ __launch_bounds__(THREADS, 1)
void fused_kernel(const float* __restrict__ floor_,
                  const float* __restrict__ keyloc,
                  const float* __restrict__ locked,
                  const int*   __restrict__ start,
                  const int*   __restrict__ goal,
                  const float* __restrict__ keygate,
                  float*       __restrict__ out)
{
    extern __shared__ float sm[];
    float* R0 = sm;                  // RR*RC
    float* R1 = sm + RR*RC;
    __shared__ float swarp[NWARP];

    const int b  = blockIdx.x;
    const int sr = start[2*b], sc = start[2*b+1];
    const int gr = min(max(goal[2*b],   0), HH-1);
    const int gc = min(max(goal[2*b+1], 0), WW-1);
    const int tid  = threadIdx.x;

    // ---- early exit: goal outside the 45-step reachable ball -> exactly 0
    const int dsg = abs(sr - gr) + abs(sc - gc);
    if (dsg > 45) {
        if (tid == 0) out[b] = 0.0f;
        return;
    }

    const int oy = sr - 49;                 // seed row -> local 49
    const int ox = (sc - 56) & ~3;          // f4-aligned; sx in [56,59]
    const int sx = sc - ox;
    const int lane = tid & 31;
    const int wid  = tid >> 5;

    // ---- zero both buffers, then seed ----
    float4* R04 = (float4*)R0;
    float4* R14 = (float4*)R1;
    const float4 z4 = make_float4(0.f,0.f,0.f,0.f);
    for (int i = tid; i < RR*RCF4; i += THREADS) { R04[i] = z4; R14[i] = z4; }
    __syncthreads();
    if (tid == 0) R0[49*RC + sx] = 1.0f;    // seed (smem)

    // ---- thread -> (f4 column v = 1..26, rows y0..y0+7 in [1,96]) ----
    const bool act = (tid < NCOLV*NGRP);    // 312 compute threads
    const int v  = 1 + tid % NCOLV;
    const int g  = min(tid / NCOLV, NGRP-1);
    const int y0 = 1 + g*RPG;
    const float kg = __ldg(keygate);
    const int gx = ox + 4*v;                // multiple of 4
    const bool colIn = ((unsigned)gx < WW);

    // per-row L1 distance to the seed (constants)
    const int dxm = max(0, max(4*v - sx, sx - (4*v + 3)));
    int dr[RPG];
    int dminT = 9999;
    #pragma unroll
    for (int i = 0; i < RPG; ++i) {
        dr[i] = abs(y0 + i - 49) + dxm;
        dminT = min(dminT, dr[i]);
    }

    // per-row L1 distance to the goal (local coords; goal inside: dsg<=45)
    const int lyg = 49 + (gr - sr);
    const int lxg = sx + (gc - sc);
    const int dgx = max(0, max(4*v - lxg, lxg - (4*v + 3)));
    int dg[RPG];
    #pragma unroll
    for (int i = 0; i < RPG; ++i) dg[i] = abs(y0 + i - lyg) + dgx;

    const float4* F4 = (const float4*)(floor_ + (size_t)b*HW);
    const float4* L4 = (const float4*)(locked + (size_t)b*HW);
    const float4* K4 = (const float4*)(keyloc + (size_t)b*HW);
    const int cf4 = gx >> 2;

    // thread-local base pointers (16B-aligned); runtime-swapped per iter
    float* pA = R0 + y0*RC + 4*v;
    float* pB = R1 + y0*RC + 4*v;
    float* curBuf = R0;              // whole-buffer pointer for the gather
    __syncthreads();

    // register state: this thread's 8 rows, read from seeded smem
    float4 O[RPG];
    #pragma unroll
    for (int i = 0; i < RPG; ++i)
        O[i] = act ? *(const float4*)(pA + i*RC) : z4;

    float keys = 0.0f;

    #pragma unroll 1
    for (int stage = 0; stage < 3; ++stage) {
        const int kend  = 15*(stage + 1);
        const int kbase = 15*stage;
        // door gate + walk into registers (per-row gated; out-of-image -> 0)
        const float dp = 1.0f / (1.0f + expf(-kg*(keys - 1.0f)));
        float4 Wd[RPG];
        #pragma unroll
        for (int i = 0; i < RPG; ++i) Wd[i] = z4;
        if (act && colIn) {
            #pragma unroll
            for (int i = 0; i < RPG; ++i) {
                int gy = oy + y0 + i;
                if (dr[i] <= kend && (unsigned)gy < HH) {
                    size_t off = (size_t)gy*W4R + cf4;
                    float4 f = __ldg(F4 + off), l = __ldg(L4 + off);
                    Wd[i].x = 0.25f*f.x*(1.0f - l.x + l.x*dp);
                    Wd[i].y = 0.25f*f.y*(1.0f - l.y + l.y*dp);
                    Wd[i].z = 0.25f*f.z*(1.0f - l.z + l.z*dp);
                    Wd[i].w = 0.25f*f.w*(1.0f - l.w + l.w*dp);
                }
            }
        }

        // 15 Jacobi iterations; rows in registers, halo via smem
        #pragma unroll 5
        for (int it = 0; it < 15; ++it) {
            const int k = kbase + it + 1;
            if (act && dminT <= k) {
                float4 U = *(const float4*)(pA - RC);       // row y0-1
                float4 D = *(const float4*)(pA + RPG*RC);   // row y0+8
                float4 Uprev = U;
                #pragma unroll
                for (int i = 0; i < RPG; ++i) {
                    float4 C  = O[i];
                    float4 Dn = (i == RPG-1) ? D : O[i+1];
                    bool on = (dr[i] <= k);
                    if (stage == 2) on = on && (dg[i] <= 14 - it);
                    if (on) {
                        float Lh = pA[i*RC - 1];
                        float Rh = pA[i*RC + 4];
                        float4 N;
                        FMASAT(N.x, (Uprev.x+Dn.x)+(Lh +C.y), Wd[i].x, C.x);
                        FMASAT(N.y, (Uprev.y+Dn.y)+(C.x+C.z), Wd[i].y, C.y);
                        FMASAT(N.z, (Uprev.z+Dn.z)+(C.y+C.w), Wd[i].z, C.z);
                        FMASAT(N.w, (Uprev.w+Dn.w)+(C.z+Rh ), Wd[i].w, C.w);
                        *(float4*)(pB + i*RC) = N;
                        O[i] = N;
                    }
                    Uprev = C;                 // old value regardless of gate
                }
            }
            __syncthreads();
            float* t = pA; pA = pB; pB = t;
        }
        curBuf = (curBuf == R0) ? R1 : R0;     // 15 (odd) swaps per stage

        // fused key reduction (stage 2's keys are dead code in the reference)
        if (stage < 2) {
            float acc = 0.0f;
            if (act && colIn && dminT <= kend) {
                #pragma unroll
                for (int i = 0; i < RPG; ++i) {
                    int gy = oy + y0 + i;
                    if (dr[i] <= kend && (unsigned)gy < HH) {
                        float4 kk = __ldg(K4 + (size_t)gy*W4R + cf4);
                        acc += (O[i].x*kk.x + O[i].y*kk.y)
                             + (O[i].z*kk.z + O[i].w*kk.w);
                    }
                }
            }
            #pragma unroll
            for (int off = 16; off > 0; off >>= 1)
                acc += __shfl_down_sync(FULL, acc, off);
            if (lane == 0) swarp[wid] = acc;
            __syncthreads();
            float s = 0.0f;
            #pragma unroll
            for (int w = 0; w < NWARP; ++w) s += swarp[w];
            keys += s;                          // identical in every thread
            // no barrier needed: swarp next written >=15 barriers from now
        }
    }

    // gather: out[b] = R at clipped goal (inside region since dsg <= 45)
    if (tid == 0) {
        int ly = gr - oy, lx = gc - ox;
        float val = 0.0f;
        if ((unsigned)ly < RR && (unsigned)lx < RC) val = curBuf[ly*RC + lx];
        out[b] = val;
    }
}

// ---------------------------------------------------------------
extern "C" void kernel_launch(void* const* d_in, const int* in_sizes, int n_in,
                              void* d_out, int out_size) {
    const float* floor_  = (const float*)d_in[0];
    const float* keyloc  = (const float*)d_in[1];
    const float* locked  = (const float*)d_in[2];
    const int*   start   = (const int*)  d_in[3];
    const int*   goal    = (const int*)  d_in[4];
    const float* keygate = (const float*)d_in[5];
    float* out = (float*)d_out;

    cudaFuncSetAttribute(fused_kernel,
                         cudaFuncAttributeMaxDynamicSharedMemorySize, SMEMB);
    fused_kernel<<<BATCH, THREADS, SMEMB>>>(floor_, keyloc, locked,
                                            start, goal, keygate, out);
}

// round 16
// speedup vs baseline: 1.8617x; 1.8617x over previous
#include <cuda_runtime.h>
#include <math.h>

#define BATCH 128
#define HH 512
#define WW 512
#define HW (HH*WW)
#define W4R (WW/4)       // 128 float4 per image row

// Per-batch compute region: 98 rows x 112 cols (floats), one CTA per batch.
// Seed at local (49, sx), sx in [56,59]. Support after k global iterations
// is the L1-diamond of radius k (forward gate). Stage 3 additionally gated
// by the backward cone of the goal. Batches with L1(start,goal)>45 exit
// immediately with out=0 (exact). Blocks are assigned to threads in
// diamond-distance order so active warps are fully active (no masked issue).
#define RR 98            // region rows
#define RC 112           // region cols (floats)
#define RCF4 (RC/4)      // 28 f4 per row
#define NCOLV 26         // compute f4 columns v = 1..26
#define NGRP 32          // row groups
#define RPG 3            // rows per group: 32*3 = 96 compute rows (1..96)
#define THREADS (NCOLV*NGRP)   // 832 (26 warps)
#define NWARP (THREADS/32)     // 26
#define SMEMB (2*RR*RC*4)      // 87,808 B dynamic
#define FULL 0xffffffffu
#define NBKT 128         // dmin buckets (dmin <= 98)

// d = clamp(a*w + c, 0, 1) in ONE instruction (FFMA.SAT)
#define FMASAT(d, a, w, c) \
    asm("fma.rn.sat.f32 %0, %1, %2, %3;" : "=f"(d) : "f"(a), "f"(w), "f"(c))

__global__ __launch_bounds__(THREADS, 1)
void fused_kernel(const float* __restrict__ floor_,
                  const float* __restrict__ keyloc,
                  const float* __restrict__ locked,
                  const int*   __restrict__ start,
                  const int*   __restrict__ goal,
                  const float* __restrict__ keygate,
                  float*       __restrict__ out)
{
    extern __shared__ float sm[];
    float* R0 = sm;                  // RR*RC
    float* R1 = sm + RR*RC;
    __shared__ float swarp[NWARP];
    __shared__ int   perm[THREADS];
    __shared__ int   cnt[NBKT];

    const int b  = blockIdx.x;
    const int sr = start[2*b], sc = start[2*b+1];
    const int gr = min(max(goal[2*b],   0), HH-1);
    const int gc = min(max(goal[2*b+1], 0), WW-1);
    const int tid  = threadIdx.x;

    // ---- early exit: goal outside the 45-step reachable ball -> exactly 0
    const int dsg = abs(sr - gr) + abs(sc - gc);
    if (dsg > 45) {
        if (tid == 0) out[b] = 0.0f;
        return;
    }

    const int oy = sr - 49;                 // seed row -> local 49
    const int ox = (sc - 56) & ~3;          // f4-aligned; sx in [56,59]
    const int sx = sc - ox;
    const int lane = tid & 31;
    const int wid  = tid >> 5;

    // ---- zero both buffers ----
    float4* R04 = (float4*)R0;
    float4* R14 = (float4*)R1;
    const float4 z4 = make_float4(0.f,0.f,0.f,0.f);
    for (int i = tid; i < RR*RCF4; i += THREADS) { R04[i] = z4; R14[i] = z4; }
    if (tid < NBKT) cnt[tid] = 0;
    __syncthreads();
    if (tid == 0) R0[49*RC + sx] = 1.0f;    // seed (smem)

    // ---- counting-sort the 832 (v,g) blocks by L1 distance to the seed ----
    {
        int v0  = 1 + tid % NCOLV;
        int g0  = tid / NCOLV;
        int y00 = 1 + g0*RPG;
        int dy0 = max(0, max(y00 - 49, 47 - y00));
        int dx0 = max(0, max(4*v0 - sx, sx - (4*v0 + 3)));
        int d0  = dy0 + dx0;
        atomicAdd(&cnt[d0], 1);
        __syncthreads();
        if (tid == 0) {                      // exclusive prefix sum
            int s = 0;
            for (int i = 0; i < NBKT; ++i) { int c = cnt[i]; cnt[i] = s; s += c; }
        }
        __syncthreads();
        int pos = atomicAdd(&cnt[d0], 1);
        perm[pos] = (v0 << 8) | g0;
    }
    __syncthreads();

    // ---- this thread's block: diamond-rank tid -> (v, g) ----
    const int code = perm[tid];
    const int v  = code >> 8;
    const int g  = code & 255;
    const int y0 = 1 + g*RPG;
    const float kg = __ldg(keygate);
    const int gx = ox + 4*v;                // multiple of 4
    const bool colIn = ((unsigned)gx < WW);

    // min L1 distance from this thread's 3x4 block to the seed (constant)
    const int dy_min = max(0, max(y0 - 49, 47 - y0));
    const int dx_min = max(0, max(4*v - sx, sx - (4*v + 3)));
    const int dmin   = dy_min + dx_min;

    // min L1 distance from this block to the goal (local coords; goal is
    // inside the region because dsg <= 45)
    const int lyg = 49 + (gr - sr);
    const int lxg = sx + (gc - sc);
    const int dgy = max(0, max(y0 - lyg, lyg - (y0 + 2)));
    const int dgx = max(0, max(4*v - lxg, lxg - (4*v + 3)));
    const int dgoal = dgy + dgx;

    const float4* F4 = (const float4*)(floor_ + (size_t)b*HW);
    const float4* L4 = (const float4*)(locked + (size_t)b*HW);
    const float4* K4 = (const float4*)(keyloc + (size_t)b*HW);
    const int cf4 = gx >> 2;

    // thread-local base pointers (16B-aligned)
    float* pA = R0 + y0*RC + 4*v;
    float* pB = R1 + y0*RC + 4*v;
    float* curBuf = R0;              // whole-buffer pointer for the gather

    // register copy of this thread's 3 rows (state). Initially zero + seed.
    float4 O0 = z4, O1 = z4, O2 = z4;
    if (sr - oy >= y0 && sr - oy <= y0 + 2 && sx >= 4*v && sx <= 4*v + 3) {
        float* Op = (sr - oy == y0) ? &O0.x : (sr - oy == y0 + 1) ? &O1.x : &O2.x;
        Op[sx - 4*v] = 1.0f;
    }

    float keys = 0.0f;
    __syncthreads();

    #pragma unroll 1
    for (int stage = 0; stage < 3; ++stage) {
        const int kend = 15*(stage + 1);
        const int drem = dmin - 15*stage;   // forward gate: drem <= it+1
        // door gate + walk into registers (gated; out-of-image -> 0)
        const float dp = 1.0f / (1.0f + expf(-kg*(keys - 1.0f)));
        float4 Wr[RPG];
        #pragma unroll
        for (int i = 0; i < RPG; ++i) Wr[i] = z4;
        if (dmin <= kend && colIn) {
            #pragma unroll
            for (int i = 0; i < RPG; ++i) {
                int gy = oy + y0 + i;
                if ((unsigned)gy < HH) {
                    size_t off = (size_t)gy*W4R + cf4;
                    float4 f = __ldg(F4 + off), l = __ldg(L4 + off);
                    Wr[i].x = 0.25f*f.x*(1.0f - l.x + l.x*dp);
                    Wr[i].y = 0.25f*f.y*(1.0f - l.y + l.y*dp);
                    Wr[i].z = 0.25f*f.z*(1.0f - l.z + l.z*dp);
                    Wr[i].w = 0.25f*f.w*(1.0f - l.w + l.w*dp);
                }
            }
        }

        // 15 Jacobi iterations, fully unrolled; buffer parity compile-time.
        // Stage 3 additionally gated by the goal's backward cone.
        #pragma unroll
        for (int it = 0; it < 15; ++it) {
            float* cu = (it & 1) ? pB : pA;
            float* nx = (it & 1) ? pA : pB;
            bool on = (drem <= it + 1);
            if (stage == 2) on = on && (dgoal <= 14 - it);
            if (on) {
                float4 U = *(const float4*)(cu - RC);
                float4 D = *(const float4*)(cu + 3*RC);
                float L0 = cu[-1],      Rh0 = cu[4];
                float L1 = cu[RC-1],    Rh1 = cu[RC+4];
                float L2 = cu[2*RC-1],  Rh2 = cu[2*RC+4];
                float4 N0, N1, N2;
                FMASAT(N0.x, (U.x +O1.x)+(L0  +O0.y), Wr[0].x, O0.x);
                FMASAT(N0.y, (U.y +O1.y)+(O0.x+O0.z), Wr[0].y, O0.y);
                FMASAT(N0.z, (U.z +O1.z)+(O0.y+O0.w), Wr[0].z, O0.z);
                FMASAT(N0.w, (U.w +O1.w)+(O0.z+Rh0 ), Wr[0].w, O0.w);
                FMASAT(N2.x, (O1.x+D.x )+(L2  +O2.y), Wr[2].x, O2.x);
                FMASAT(N2.y, (O1.y+D.y )+(O2.x+O2.z), Wr[2].y, O2.y);
                FMASAT(N2.z, (O1.z+D.z )+(O2.y+O2.w), Wr[2].z, O2.z);
                FMASAT(N2.w, (O1.w+D.w )+(O2.z+Rh2 ), Wr[2].w, O2.w);
                *(float4*)(nx)        = N0;   // boundary rows first
                *(float4*)(nx + 2*RC) = N2;
                FMASAT(N1.x, (O0.x+O2.x)+(L1  +O1.y), Wr[1].x, O1.x);
                FMASAT(N1.y, (O0.y+O2.y)+(O1.x+O1.z), Wr[1].y, O1.y);
                FMASAT(N1.z, (O0.z+O2.z)+(O1.y+O1.w), Wr[1].z, O1.z);
                FMASAT(N1.w, (O0.w+O2.w)+(O1.z+Rh1 ), Wr[1].w, O1.w);
                *(float4*)(nx + RC)   = N1;
                O0 = N0; O1 = N1; O2 = N2;
            }
            __syncthreads();
        }
        // 15 iterations (odd) -> state ended in the B-parity buffer; swap.
        { float* t = pA; pA = pB; pB = t; }
        curBuf = (curBuf == R0) ? R1 : R0;

        // fused key reduction (stage 2's keys are dead code in the reference)
        if (stage < 2) {
            float acc = 0.0f;
            if (dmin <= kend && colIn) {        // R==0 beyond radius kend
                #pragma unroll
                for (int i = 0; i < RPG; ++i) {
                    int gy = oy + y0 + i;
                    if ((unsigned)gy < HH) {
                        float4 r = (i == 0) ? O0 : (i == 1) ? O1 : O2;
                        float4 kk = __ldg(K4 + (size_t)gy*W4R + cf4);
                        acc += (r.x*kk.x + r.y*kk.y) + (r.z*kk.z + r.w*kk.w);
                    }
                }
            }
            #pragma unroll
            for (int off = 16; off > 0; off >>= 1)
                acc += __shfl_down_sync(FULL, acc, off);
            if (lane == 0) swarp[wid] = acc;
            __syncthreads();
            float s = 0.0f;
            #pragma unroll
            for (int w = 0; w < NWARP; ++w) s += swarp[w];
            keys += s;                          // identical in every thread
            // no barrier needed: swarp next written >=15 barriers from now
        }
    }

    // gather: out[b] = R at clipped goal (inside region since dsg <= 45)
    if (tid == 0) {
        int ly = gr - oy, lx = gc - ox;
        float val = 0.0f;
        if ((unsigned)ly < RR && (unsigned)lx < RC) val = curBuf[ly*RC + lx];
        out[b] = val;
    }
}

// ---------------------------------------------------------------
extern "C" void kernel_launch(void* const* d_in, const int* in_sizes, int n_in,
                              void* d_out, int out_size) {
    const float* floor_  = (const float*)d_in[0];
    const float* keyloc  = (const float*)d_in[1];
    const float* locked  = (const float*)d_in[2];
    const int*   start   = (const int*)  d_in[3];
    const int*   goal    = (const int*)  d_in[4];
    const float* keygate = (const float*)d_in[5];
    float* out = (float*)d_out;

    cudaFuncSetAttribute(fused_kernel,
                         cudaFuncAttributeMaxDynamicSharedMemorySize, SMEMB);
    fused_kernel<<<BATCH, THREADS, SMEMB>>>(floor_, keyloc, locked,
                                            start, goal, keygate, out);
}